// round 12
// baseline (speedup 1.0000x reference)
#include <cuda_runtime.h>
#include <cuda_fp16.h>
#include <math.h>
#include <stdint.h>

// ---------------------------------------------------------------- constants
#define B_    8
#define L_    4096
#define H_    16
#define DH_   64
#define DM_   1024
#define MTOK  (B_ * L_)          // 32768
#define QKVN  (3 * H_ * DH_)     // 3072
#define KDIM  1024

// ---------------------------------------------------------------- scratch
__device__ __align__(16) __half g_qkvh[(size_t)MTOK * QKVN];  // fp16 qkv (201 MB)
__device__ float  g_pe[L_ * DH_];
__device__ __align__(16) __half g_x[(size_t)MTOK * DM_];      // x -> fp16
__device__ __align__(16) __half g_c[(size_t)MTOK * DM_];      // attn-out fp16
__device__ __align__(16) __half g_w1[(size_t)QKVN * DM_];     // w_qkv^T fp16
__device__ __align__(16) __half g_w2[(size_t)DM_ * DM_];      // w_out^T fp16

// ---------------------------------------------------------------- helpers
__device__ __forceinline__ uint32_t smem_u32(const void* p) {
    uint32_t a;
    asm("{ .reg .u64 t; cvta.to.shared.u64 t, %1; cvt.u32.u64 %0, t; }" : "=r"(a) : "l"(p));
    return a;
}
__device__ __forceinline__ void cp16(uint32_t dst, const void* src) {
    asm volatile("cp.async.cg.shared.global [%0], [%1], 16;" :: "r"(dst), "l"(src));
}
#define CP_COMMIT() asm volatile("cp.async.commit_group;" ::: "memory")
#define CP_WAIT1()  asm volatile("cp.async.wait_group 1;" ::: "memory")

__device__ __forceinline__ void ldm_x4(uint32_t* r, uint32_t addr) {
    asm volatile("ldmatrix.sync.aligned.m8n8.x4.shared.b16 {%0,%1,%2,%3}, [%4];"
                 : "=r"(r[0]), "=r"(r[1]), "=r"(r[2]), "=r"(r[3]) : "r"(addr));
}
__device__ __forceinline__ void mma16816(float* c, const uint32_t* a, const uint32_t* b) {
    asm volatile(
        "mma.sync.aligned.m16n8k16.row.col.f32.f16.f16.f32 "
        "{%0,%1,%2,%3}, {%4,%5,%6,%7}, {%8,%9}, {%0,%1,%2,%3};"
        : "+f"(c[0]), "+f"(c[1]), "+f"(c[2]), "+f"(c[3])
        : "r"(a[0]), "r"(a[1]), "r"(a[2]), "r"(a[3]), "r"(b[0]), "r"(b[1]));
}
// fp16-accumulate variant: D,C are 2 regs holding 4 halves
__device__ __forceinline__ void mma16816h(uint32_t* c, const uint32_t* a, const uint32_t* b) {
    asm volatile(
        "mma.sync.aligned.m16n8k16.row.col.f16.f16.f16.f16 "
        "{%0,%1}, {%2,%3,%4,%5}, {%6,%7}, {%0,%1};"
        : "+r"(c[0]), "+r"(c[1])
        : "r"(a[0]), "r"(a[1]), "r"(a[2]), "r"(a[3]), "r"(b[0]), "r"(b[1]));
}

// ---------------------------------------------------------------- pe table
__global__ void pe_init_kernel() {
    int idx = blockIdx.x * blockDim.x + threadIdx.x;
    if (idx >= L_ * (DH_ / 2)) return;
    int l = idx >> 5;
    int j = idx & 31;
    float c    = (float)(-9.210340371976184 / 64.0);
    float argf = c * (float)(2 * j);
    float dtf  = (float)exp((double)argf);
    float angf = (float)((double)l * (double)dtf);
    double ang = (double)angf;
    g_pe[l * DH_ + 2 * j]     = (float)sin(ang);
    g_pe[l * DH_ + 2 * j + 1] = (float)cos(ang);
}

// ---------------------------------------------------------------- casts
__global__ void cast_f2h_kernel(const float* __restrict__ in,
                                __half* __restrict__ out, int n4) {
    int i = blockIdx.x * blockDim.x + threadIdx.x;
    if (i >= n4) return;
    float4 v = ((const float4*)in)[i];
    ((__half2*)out)[2 * i]     = __floats2half2_rn(v.x, v.y);
    ((__half2*)out)[2 * i + 1] = __floats2half2_rn(v.z, v.w);
}

// transpose [K,N] -> [N,K] + fp16 cast.  block (32,8), grid (N/32, K/32)
__global__ void transpose_cast_kernel(const float* __restrict__ w,
                                      __half* __restrict__ t,
                                      int K, int N) {
    __shared__ float tile[32][33];
    int nb = blockIdx.x * 32, kb = blockIdx.y * 32;
    int tx = threadIdx.x, ty = threadIdx.y;
#pragma unroll
    for (int j = 0; j < 4; j++)
        tile[ty + 8 * j][tx] = w[(size_t)(kb + ty + 8 * j) * N + nb + tx];
    __syncthreads();
#pragma unroll
    for (int j = 0; j < 4; j++) {
        int n = nb + ty + 8 * j;
        int k = kb + tx;
        t[(size_t)n * K + k] = __float2half(tile[tx][ty + 8 * j]);
    }
}

// ---------------------------------------------------------------- HMMA GEMM
// C[M,N] = A[M,1024](fp16) @ B[N,1024]^T(fp16) + bias.  OutT in {__half,float}.
// HACC: accumulate each KB=64 chunk in fp16 (2x rate if HW supports), spill
// to fp32 once per iteration.
// CTA tile 128x128, warp tile 64x32 (8 warps 2x4), KB=64, 3-stage cp.async,
// 2 CTAs/SM, single barrier per iter, prefetch before MMA section.
#define BM    128
#define BN    128
#define KB    64
#define NITER (KDIM / KB)        // 16
#define ROWH  72                 // 64 halfs + pad 8
#define ROWB  (ROWH * 2)         // 144 bytes
#define TILEB (BM * ROWB)        // 18432 B
#define STB   (2 * TILEB)        // A + B = 36864 B
#define SMTOT (3 * STB)          // 110592 B

__device__ __forceinline__ void cp_tile(uint32_t s_tile, const __half* g,
                                        int kc, int tid) {
    int r0 = tid >> 3;           // 0..31
    int c  = tid & 7;
    const __half* gp = g + (size_t)r0 * KDIM + kc * KB + c * 8;
    uint32_t sp = s_tile + (uint32_t)r0 * ROWB + c * 16;
#pragma unroll
    for (int i = 0; i < 4; i++)
        cp16(sp + i * 32 * ROWB, gp + (size_t)(i * 32) * KDIM);
}

template<typename OutT, bool HACC>
__global__ __launch_bounds__(256, 2)
void hmma_gemm_kernel(const __half* __restrict__ A,
                      const __half* __restrict__ B,
                      const float* __restrict__ bias,
                      OutT* __restrict__ C,
                      int ncols)
{
    extern __shared__ __align__(16) char smem[];
    const uint32_t sb = smem_u32(smem);
    const int tid  = threadIdx.x;
    const int wid  = tid >> 5;
    const int lane = tid & 31;
    const int wrow = wid >> 2;       // 0..1  (64 rows each)
    const int wcol = wid & 3;        // 0..3  (32 cols each)
    const int bm   = blockIdx.y * BM;
    const int bn   = blockIdx.x * BN;

    const __half* gA = A + (size_t)bm * KDIM;
    const __half* gB = B + (size_t)bn * KDIM;

    float acc[4][4][4];
#pragma unroll
    for (int i = 0; i < 4; i++)
#pragma unroll
        for (int j = 0; j < 4; j++)
#pragma unroll
            for (int k = 0; k < 4; k++) acc[i][j][k] = 0.0f;

    const uint32_t a_row  = (uint32_t)(wrow * 64 + (lane & 15));
    const uint32_t a_col  = (uint32_t)((lane >> 4) * 8);
    const uint32_t b_row4 = (uint32_t)(wcol * 32 + (lane >> 4) * 8 + (lane & 7));
    const uint32_t b_col4 = (uint32_t)(((lane >> 3) & 1) * 8);

#define LOADST(buf, kc) do {                                    \
        uint32_t s0 = sb + (buf) * STB;                         \
        cp_tile(s0,         gA, (kc), tid);                     \
        cp_tile(s0 + TILEB, gB, (kc), tid);                     \
    } while (0)

    LOADST(0, 0); CP_COMMIT();
    LOADST(1, 1); CP_COMMIT();

    for (int it = 0; it < NITER; ++it) {
        CP_WAIT1();
        __syncthreads();
        int buf = it % 3;
        int pre = (buf + 2) % 3;
        if (it + 2 < NITER) LOADST(pre, it + 2);
        CP_COMMIT();

        uint32_t s0 = sb + buf * STB;
        uint32_t sA = s0;
        uint32_t sB = s0 + TILEB;

        if constexpr (HACC) {
            uint32_t hacc[4][4][2];
#pragma unroll
            for (int i = 0; i < 4; i++)
#pragma unroll
                for (int j = 0; j < 4; j++)
                    hacc[i][j][0] = hacc[i][j][1] = 0u;

#pragma unroll
            for (int ks = 0; ks < 4; ks++) {
                uint32_t af[4][4], bf[2][4];
                uint32_t acol = (uint32_t)(ks * 32) + a_col * 2;
                uint32_t bcol = (uint32_t)(ks * 32) + b_col4 * 2;
#pragma unroll
                for (int ma = 0; ma < 4; ma++)
                    ldm_x4(af[ma], sA + (a_row + ma * 16) * ROWB + acol);
#pragma unroll
                for (int nb2 = 0; nb2 < 2; nb2++)
                    ldm_x4(bf[nb2], sB + (b_row4 + nb2 * 16) * ROWB + bcol);
#pragma unroll
                for (int ma = 0; ma < 4; ma++)
#pragma unroll
                    for (int na = 0; na < 4; na++)
                        mma16816h(hacc[ma][na], af[ma], &bf[na >> 1][(na & 1) * 2]);
            }
            // spill fp16 chunk accum into fp32 accumulators
#pragma unroll
            for (int ma = 0; ma < 4; ma++)
#pragma unroll
                for (int na = 0; na < 4; na++) {
                    float2 lo = __half22float2(*(__half2*)&hacc[ma][na][0]);
                    float2 hi = __half22float2(*(__half2*)&hacc[ma][na][1]);
                    acc[ma][na][0] += lo.x;
                    acc[ma][na][1] += lo.y;
                    acc[ma][na][2] += hi.x;
                    acc[ma][na][3] += hi.y;
                }
        } else {
#pragma unroll
            for (int ks = 0; ks < 4; ks++) {
                uint32_t af[4][4], bf[2][4];
                uint32_t acol = (uint32_t)(ks * 32) + a_col * 2;
                uint32_t bcol = (uint32_t)(ks * 32) + b_col4 * 2;
#pragma unroll
                for (int ma = 0; ma < 4; ma++)
                    ldm_x4(af[ma], sA + (a_row + ma * 16) * ROWB + acol);
#pragma unroll
                for (int nb2 = 0; nb2 < 2; nb2++)
                    ldm_x4(bf[nb2], sB + (b_row4 + nb2 * 16) * ROWB + bcol);
#pragma unroll
                for (int ma = 0; ma < 4; ma++)
#pragma unroll
                    for (int na = 0; na < 4; na++)
                        mma16816(acc[ma][na], af[ma], &bf[na >> 1][(na & 1) * 2]);
            }
        }
    }

    // epilogue: bias + store (fp32 or fp16)
    const int qr = lane >> 2;
    const int qc = (lane & 3) * 2;
#pragma unroll
    for (int na = 0; na < 4; na++) {
        int col = bn + wcol * 32 + na * 8 + qc;
        float bx = bias[col], by = bias[col + 1];
#pragma unroll
        for (int ma = 0; ma < 4; ma++) {
            int r0 = bm + wrow * 64 + ma * 16 + qr;
            if constexpr (sizeof(OutT) == 2) {
                __half* Ch = (__half*)C;
                *(__half2*)(Ch + (size_t)r0 * ncols + col) =
                    __floats2half2_rn(acc[ma][na][0] + bx, acc[ma][na][1] + by);
                *(__half2*)(Ch + (size_t)(r0 + 8) * ncols + col) =
                    __floats2half2_rn(acc[ma][na][2] + bx, acc[ma][na][3] + by);
            } else {
                float* Cf = (float*)C;
                *(float2*)(Cf + (size_t)r0 * ncols + col) =
                    make_float2(acc[ma][na][0] + bx, acc[ma][na][1] + by);
                *(float2*)(Cf + (size_t)(r0 + 8) * ncols + col) =
                    make_float2(acc[ma][na][2] + bx, acc[ma][na][3] + by);
            }
        }
    }
}

// ---------------------------------------------------------------- attention
__global__ __launch_bounds__(256)
void attn_kernel() {
    __shared__ __align__(16) __half s[QKVN];
    __shared__ float spe[DH_];
    __shared__ float s_logit[256];
    __shared__ float s_prob[256];

    const int tok = blockIdx.x;
    const int l   = tok & (L_ - 1);
    const int tid = threadIdx.x;

    const uint4* row = (const uint4*)(g_qkvh + (size_t)tok * QKVN);
    uint4* s4 = (uint4*)s;
    for (int i = tid; i < QKVN * 2 / 16; i += 256)
        s4[i] = row[i];
    if (tid < DH_) spe[tid] = g_pe[l * DH_ + tid];
    __syncthreads();

    {
        const int h  = tid >> 4, gg = tid & 15;
        const __half2* q  = (const __half2*)&s[h * 192];
        const __half2* kk = (const __half2*)&s[gg * 192 + 64];
        const float2*  p2 = (const float2*)spe;
        float a = 0.0f;
#pragma unroll
        for (int i = 0; i < 32; i++) {
            int d2 = (i + gg * 2) & 31;
            float2 qf = __half22float2(q[d2]);
            float2 kf = __half22float2(kk[d2]);
            float2 pf = p2[d2];
            a += qf.x * (kf.x + pf.x) + qf.y * (kf.y + pf.y);
        }
        s_logit[tid] = a * 0.125f;
    }
    __syncthreads();

    if (tid < H_) {
        float m = -1e30f;
#pragma unroll
        for (int gg = 0; gg < 16; gg++) m = fmaxf(m, s_logit[tid * 16 + gg]);
        float p[16];
        float sum = 0.0f;
#pragma unroll
        for (int gg = 0; gg < 16; gg++) {
            p[gg] = expf(s_logit[tid * 16 + gg] - m);
            sum += p[gg];
        }
        float inv = 1.0f / sum;
#pragma unroll
        for (int gg = 0; gg < 16; gg++) s_prob[tid * 16 + gg] = p[gg] * inv;
    }
    __syncthreads();

    __half2* orow = (__half2*)(g_c + (size_t)tok * DM_);
    for (int idx = tid; idx < 512; idx += 256) {
        int h = idx >> 5, d2 = idx & 31;
        float ax = 0.0f, ay = 0.0f;
#pragma unroll
        for (int gg = 0; gg < 16; gg++) {
            float2 vf = __half22float2(((const __half2*)&s[gg * 192 + 128])[d2]);
            float p = s_prob[h * 16 + gg];
            ax += p * vf.x;
            ay += p * vf.y;
        }
        orow[idx] = __floats2half2_rn(ax, ay);
    }
}

// ---------------------------------------------------------------- launch
extern "C" void kernel_launch(void* const* d_in, const int* in_sizes, int n_in,
                              void* d_out, int out_size)
{
    (void)in_sizes; (void)n_in; (void)out_size;
    const float* x     = (const float*)d_in[0];
    const float* w_qkv = (const float*)d_in[1];
    const float* b_qkv = (const float*)d_in[2];
    const float* w_out = (const float*)d_in[3];
    const float* b_out = (const float*)d_in[4];
    float* out = (float*)d_out;

    __half *qkv_p, *xp, *cp, *w1, *w2;
    cudaGetSymbolAddress((void**)&qkv_p, g_qkvh);
    cudaGetSymbolAddress((void**)&xp, g_x);
    cudaGetSymbolAddress((void**)&cp, g_c);
    cudaGetSymbolAddress((void**)&w1, g_w1);
    cudaGetSymbolAddress((void**)&w2, g_w2);

    static bool attr_done = false;
    if (!attr_done) {
        cudaFuncSetAttribute(hmma_gemm_kernel<__half, true>,
                             cudaFuncAttributeMaxDynamicSharedMemorySize, SMTOT);
        cudaFuncSetAttribute(hmma_gemm_kernel<float, false>,
                             cudaFuncAttributeMaxDynamicSharedMemorySize, SMTOT);
        attr_done = true;
    }

    // 1. positional-encoding table
    pe_init_kernel<<<(L_ * (DH_ / 2) + 255) / 256, 256>>>();

    // 2. casts / weight transpose
    int n4 = MTOK * DM_ / 4;
    cast_f2h_kernel<<<(n4 + 255) / 256, 256>>>(x, xp, n4);
    transpose_cast_kernel<<<dim3(QKVN / 32, KDIM / 32), dim3(32, 8)>>>(w_qkv, w1, KDIM, QKVN);
    transpose_cast_kernel<<<dim3(DM_ / 32, KDIM / 32), dim3(32, 8)>>>(w_out, w2, KDIM, DM_);

    // 3. qkv projection (HMMA, fp16 chunk-accumulate): [32768,1024]@[1024,3072]+b
    hmma_gemm_kernel<__half, true><<<dim3(QKVN / BN, MTOK / BM), 256, SMTOT>>>(
        xp, w1, b_qkv, qkv_p, QKVN);

    // 4. per-token cross-head attention (fp16 in/out)
    attn_kernel<<<MTOK, 256>>>();

    // 5. output projection (HMMA, fp32 acc): [32768,1024] @ [1024,1024] + b
    hmma_gemm_kernel<float, false><<<dim3(DM_ / BN, MTOK / BM), 256, SMTOT>>>(
        cp, w2, b_out, out, DM_);
}

// round 13
// speedup vs baseline: 1.0745x; 1.0745x over previous
#include <cuda_runtime.h>
#include <cuda_fp16.h>
#include <math.h>
#include <stdint.h>

// ---------------------------------------------------------------- constants
#define B_    8
#define L_    4096
#define H_    16
#define DH_   64
#define DM_   1024
#define MTOK  (B_ * L_)          // 32768
#define QKVN  (3 * H_ * DH_)     // 3072
#define KDIM  1024

// ---------------------------------------------------------------- scratch
__device__ __align__(16) __half g_qkvh[(size_t)MTOK * QKVN];  // fp16 qkv (201 MB)
__device__ float  g_pe[L_ * DH_];
__device__ __align__(16) __half g_x[(size_t)MTOK * DM_];      // x -> fp16
__device__ __align__(16) __half g_c[(size_t)MTOK * DM_];      // attn-out fp16
__device__ __align__(16) __half g_w1[(size_t)QKVN * DM_];     // w_qkv^T fp16
__device__ __align__(16) __half g_w2[(size_t)DM_ * DM_];      // w_out^T fp16

// ---------------------------------------------------------------- helpers
__device__ __forceinline__ uint32_t smem_u32(const void* p) {
    uint32_t a;
    asm("{ .reg .u64 t; cvta.to.shared.u64 t, %1; cvt.u32.u64 %0, t; }" : "=r"(a) : "l"(p));
    return a;
}
__device__ __forceinline__ void cp16(uint32_t dst, const void* src) {
    asm volatile("cp.async.cg.shared.global [%0], [%1], 16;" :: "r"(dst), "l"(src));
}
#define CP_COMMIT() asm volatile("cp.async.commit_group;" ::: "memory")
#define CP_WAIT1()  asm volatile("cp.async.wait_group 1;" ::: "memory")

__device__ __forceinline__ void ldm_x4(uint32_t* r, uint32_t addr) {
    asm volatile("ldmatrix.sync.aligned.m8n8.x4.shared.b16 {%0,%1,%2,%3}, [%4];"
                 : "=r"(r[0]), "=r"(r[1]), "=r"(r[2]), "=r"(r[3]) : "r"(addr));
}
__device__ __forceinline__ void mma16816(float* c, const uint32_t* a, const uint32_t* b) {
    asm volatile(
        "mma.sync.aligned.m16n8k16.row.col.f32.f16.f16.f32 "
        "{%0,%1,%2,%3}, {%4,%5,%6,%7}, {%8,%9}, {%0,%1,%2,%3};"
        : "+f"(c[0]), "+f"(c[1]), "+f"(c[2]), "+f"(c[3])
        : "r"(a[0]), "r"(a[1]), "r"(a[2]), "r"(a[3]), "r"(b[0]), "r"(b[1]));
}

// ---------------------------------------------------------------- pe table
__global__ void pe_init_kernel() {
    int idx = blockIdx.x * blockDim.x + threadIdx.x;
    if (idx >= L_ * (DH_ / 2)) return;
    int l = idx >> 5;
    int j = idx & 31;
    float c    = (float)(-9.210340371976184 / 64.0);
    float argf = c * (float)(2 * j);
    float dtf  = (float)exp((double)argf);
    float angf = (float)((double)l * (double)dtf);
    double ang = (double)angf;
    g_pe[l * DH_ + 2 * j]     = (float)sin(ang);
    g_pe[l * DH_ + 2 * j + 1] = (float)cos(ang);
}

// ---------------------------------------------------------------- casts
__global__ void cast_f2h_kernel(const float* __restrict__ in,
                                __half* __restrict__ out, int n4) {
    int i = blockIdx.x * blockDim.x + threadIdx.x;
    if (i >= n4) return;
    float4 v = ((const float4*)in)[i];
    ((__half2*)out)[2 * i]     = __floats2half2_rn(v.x, v.y);
    ((__half2*)out)[2 * i + 1] = __floats2half2_rn(v.z, v.w);
}

// transpose [K,N] -> [N,K] + fp16 cast.  block (32,8), grid (N/32, K/32)
__global__ void transpose_cast_kernel(const float* __restrict__ w,
                                      __half* __restrict__ t,
                                      int K, int N) {
    __shared__ float tile[32][33];
    int nb = blockIdx.x * 32, kb = blockIdx.y * 32;
    int tx = threadIdx.x, ty = threadIdx.y;
#pragma unroll
    for (int j = 0; j < 4; j++)
        tile[ty + 8 * j][tx] = w[(size_t)(kb + ty + 8 * j) * N + nb + tx];
    __syncthreads();
#pragma unroll
    for (int j = 0; j < 4; j++) {
        int n = nb + ty + 8 * j;
        int k = kb + tx;
        t[(size_t)n * K + k] = __float2half(tile[tx][ty + 8 * j]);
    }
}

// ---------------------------------------------------------------- HMMA GEMM
// C[M,N] = A[M,1024](fp16) @ B[N,1024]^T(fp16) + bias.  OutT in {__half,float}.
// CTA tile 128x128, warp tile 64x32 (8 warps 2x4), KB=64, 3-stage cp.async,
// 2 CTAs/SM.  Single barrier per iter, prefetch issued before MMA section.
#define BM    128
#define BN    128
#define KB    64
#define NITER (KDIM / KB)        // 16
#define ROWH  72                 // 64 halfs + pad 8
#define ROWB  (ROWH * 2)         // 144 bytes
#define TILEB (BM * ROWB)        // 18432 B
#define STB   (2 * TILEB)        // A + B = 36864 B
#define SMTOT (3 * STB)          // 110592 B

__device__ __forceinline__ void cp_tile(uint32_t s_tile, const __half* g,
                                        int kc, int tid) {
    int r0 = tid >> 3;           // 0..31
    int c  = tid & 7;
    const __half* gp = g + (size_t)r0 * KDIM + kc * KB + c * 8;
    uint32_t sp = s_tile + (uint32_t)r0 * ROWB + c * 16;
#pragma unroll
    for (int i = 0; i < 4; i++)
        cp16(sp + i * 32 * ROWB, gp + (size_t)(i * 32) * KDIM);
}

template<typename OutT>
__global__ __launch_bounds__(256, 2)
void hmma_gemm_kernel(const __half* __restrict__ A,
                      const __half* __restrict__ B,
                      const float* __restrict__ bias,
                      OutT* __restrict__ C,
                      int ncols)
{
    extern __shared__ __align__(16) char smem[];
    const uint32_t sb = smem_u32(smem);
    const int tid  = threadIdx.x;
    const int wid  = tid >> 5;
    const int lane = tid & 31;
    const int wrow = wid >> 2;       // 0..1  (64 rows each)
    const int wcol = wid & 3;        // 0..3  (32 cols each)
    const int bm   = blockIdx.y * BM;
    const int bn   = blockIdx.x * BN;

    const __half* gA = A + (size_t)bm * KDIM;
    const __half* gB = B + (size_t)bn * KDIM;

    float acc[4][4][4];
#pragma unroll
    for (int i = 0; i < 4; i++)
#pragma unroll
        for (int j = 0; j < 4; j++)
#pragma unroll
            for (int k = 0; k < 4; k++) acc[i][j][k] = 0.0f;

    const uint32_t a_row  = (uint32_t)(wrow * 64 + (lane & 15));
    const uint32_t a_col  = (uint32_t)((lane >> 4) * 8);
    const uint32_t b_row4 = (uint32_t)(wcol * 32 + (lane >> 4) * 8 + (lane & 7));
    const uint32_t b_col4 = (uint32_t)(((lane >> 3) & 1) * 8);

#define LOADST(buf, kc) do {                                    \
        uint32_t s0 = sb + (buf) * STB;                         \
        cp_tile(s0,         gA, (kc), tid);                     \
        cp_tile(s0 + TILEB, gB, (kc), tid);                     \
    } while (0)

    LOADST(0, 0); CP_COMMIT();
    LOADST(1, 1); CP_COMMIT();

    for (int it = 0; it < NITER; ++it) {
        CP_WAIT1();
        __syncthreads();
        int buf = it % 3;
        int pre = (buf + 2) % 3;
        if (it + 2 < NITER) LOADST(pre, it + 2);
        CP_COMMIT();

        uint32_t s0 = sb + buf * STB;
        uint32_t sA = s0;
        uint32_t sB = s0 + TILEB;

#pragma unroll
        for (int ks = 0; ks < 4; ks++) {
            uint32_t af[4][4], bf[2][4];
            uint32_t acol = (uint32_t)(ks * 32) + a_col * 2;
            uint32_t bcol = (uint32_t)(ks * 32) + b_col4 * 2;
#pragma unroll
            for (int ma = 0; ma < 4; ma++)
                ldm_x4(af[ma], sA + (a_row + ma * 16) * ROWB + acol);
#pragma unroll
            for (int nb2 = 0; nb2 < 2; nb2++)
                ldm_x4(bf[nb2], sB + (b_row4 + nb2 * 16) * ROWB + bcol);
#pragma unroll
            for (int ma = 0; ma < 4; ma++)
#pragma unroll
                for (int na = 0; na < 4; na++)
                    mma16816(acc[ma][na], af[ma], &bf[na >> 1][(na & 1) * 2]);
        }
    }

    // epilogue: bias + store (fp32 or fp16)
    const int qr = lane >> 2;
    const int qc = (lane & 3) * 2;
#pragma unroll
    for (int na = 0; na < 4; na++) {
        int col = bn + wcol * 32 + na * 8 + qc;
        float bx = bias[col], by = bias[col + 1];
#pragma unroll
        for (int ma = 0; ma < 4; ma++) {
            int r0 = bm + wrow * 64 + ma * 16 + qr;
            if constexpr (sizeof(OutT) == 2) {
                __half* Ch = (__half*)C;
                *(__half2*)(Ch + (size_t)r0 * ncols + col) =
                    __floats2half2_rn(acc[ma][na][0] + bx, acc[ma][na][1] + by);
                *(__half2*)(Ch + (size_t)(r0 + 8) * ncols + col) =
                    __floats2half2_rn(acc[ma][na][2] + bx, acc[ma][na][3] + by);
            } else {
                float* Cf = (float*)C;
                *(float2*)(Cf + (size_t)r0 * ncols + col) =
                    make_float2(acc[ma][na][0] + bx, acc[ma][na][1] + by);
                *(float2*)(Cf + (size_t)(r0 + 8) * ncols + col) =
                    make_float2(acc[ma][na][2] + bx, acc[ma][na][3] + by);
            }
        }
    }
}

// ---------------------------------------------------------------- attention
// TWO tokens per 256-thread block (tokens 2b, 2b+1 are contiguous rows).
__global__ __launch_bounds__(256)
void attn2_kernel() {
    __shared__ __align__(16) __half s[2][QKVN];   // 12 KB
    __shared__ float spe[2][DH_];
    __shared__ float s_logit[512];
    __shared__ float s_prob[512];

    const int t0  = blockIdx.x * 2;
    const int tid = threadIdx.x;

    // load both token rows (contiguous 12288 B)
    const uint4* row = (const uint4*)(g_qkvh + (size_t)t0 * QKVN);
    uint4* s4 = (uint4*)&s[0][0];
#pragma unroll
    for (int i = 0; i < 3; i++)
        s4[tid + 256 * i] = row[tid + 256 * i];
    if (tid < 2 * DH_) {
        int tt = tid >> 6, d = tid & 63;
        spe[tt][d] = g_pe[((t0 + tt) & (L_ - 1)) * DH_ + d];
    }
    __syncthreads();

    // logits: 512 items (tt, h, g); k-row access skewed by g
#pragma unroll
    for (int rep = 0; rep < 2; rep++) {
        const int idx = tid + rep * 256;
        const int tt = idx >> 8, h = (idx >> 4) & 15, gg = idx & 15;
        const __half2* q  = (const __half2*)&s[tt][h * 192];
        const __half2* kk = (const __half2*)&s[tt][gg * 192 + 64];
        const float2*  p2 = (const float2*)spe[tt];
        float a = 0.0f;
#pragma unroll
        for (int i = 0; i < 32; i++) {
            int d2 = (i + gg * 2) & 31;
            float2 qf = __half22float2(q[d2]);
            float2 kf = __half22float2(kk[d2]);
            float2 pf = p2[d2];
            a += qf.x * (kf.x + pf.x) + qf.y * (kf.y + pf.y);
        }
        s_logit[idx] = a * 0.125f;
    }
    __syncthreads();

    // softmax: 32 threads, one per (tt, h)
    if (tid < 2 * H_) {
        const int base = tid * 16;     // tt*256 + h*16
        float m = -1e30f;
#pragma unroll
        for (int gg = 0; gg < 16; gg++) m = fmaxf(m, s_logit[base + gg]);
        float p[16];
        float sum = 0.0f;
#pragma unroll
        for (int gg = 0; gg < 16; gg++) {
            p[gg] = expf(s_logit[base + gg] - m);
            sum += p[gg];
        }
        float inv = 1.0f / sum;
#pragma unroll
        for (int gg = 0; gg < 16; gg++) s_prob[base + gg] = p[gg] * inv;
    }
    __syncthreads();

    // mix: 1024 half2 outputs (2 tokens x 512)
    __half2* orow = (__half2*)(g_c + (size_t)t0 * DM_);
#pragma unroll
    for (int rep = 0; rep < 4; rep++) {
        const int idx = tid + rep * 256;
        const int tt = idx >> 9, rem = idx & 511;
        const int h = rem >> 5, d2 = rem & 31;
        const float* pr = &s_prob[tt * 256 + h * 16];
        const __half2* vv;
        float ax = 0.0f, ay = 0.0f;
#pragma unroll
        for (int gg = 0; gg < 16; gg++) {
            vv = (const __half2*)&s[tt][gg * 192 + 128];
            float2 vf = __half22float2(vv[d2]);
            float p = pr[gg];
            ax += p * vf.x;
            ay += p * vf.y;
        }
        orow[(size_t)tt * (DM_ / 2) + rem] = __floats2half2_rn(ax, ay);
    }
}

// ---------------------------------------------------------------- launch
extern "C" void kernel_launch(void* const* d_in, const int* in_sizes, int n_in,
                              void* d_out, int out_size)
{
    (void)in_sizes; (void)n_in; (void)out_size;
    const float* x     = (const float*)d_in[0];
    const float* w_qkv = (const float*)d_in[1];
    const float* b_qkv = (const float*)d_in[2];
    const float* w_out = (const float*)d_in[3];
    const float* b_out = (const float*)d_in[4];
    float* out = (float*)d_out;

    __half *qkv_p, *xp, *cp, *w1, *w2;
    cudaGetSymbolAddress((void**)&qkv_p, g_qkvh);
    cudaGetSymbolAddress((void**)&xp, g_x);
    cudaGetSymbolAddress((void**)&cp, g_c);
    cudaGetSymbolAddress((void**)&w1, g_w1);
    cudaGetSymbolAddress((void**)&w2, g_w2);

    static bool attr_done = false;
    if (!attr_done) {
        cudaFuncSetAttribute(hmma_gemm_kernel<__half>,
                             cudaFuncAttributeMaxDynamicSharedMemorySize, SMTOT);
        cudaFuncSetAttribute(hmma_gemm_kernel<float>,
                             cudaFuncAttributeMaxDynamicSharedMemorySize, SMTOT);
        attr_done = true;
    }

    // 1. positional-encoding table
    pe_init_kernel<<<(L_ * (DH_ / 2) + 255) / 256, 256>>>();

    // 2. casts / weight transpose
    int n4 = MTOK * DM_ / 4;
    cast_f2h_kernel<<<(n4 + 255) / 256, 256>>>(x, xp, n4);
    transpose_cast_kernel<<<dim3(QKVN / 32, KDIM / 32), dim3(32, 8)>>>(w_qkv, w1, KDIM, QKVN);
    transpose_cast_kernel<<<dim3(DM_ / 32, KDIM / 32), dim3(32, 8)>>>(w_out, w2, KDIM, DM_);

    // 3. qkv projection (HMMA, fp16 out): [32768,1024] @ [1024,3072] + b
    hmma_gemm_kernel<__half><<<dim3(QKVN / BN, MTOK / BM), 256, SMTOT>>>(
        xp, w1, b_qkv, qkv_p, QKVN);

    // 4. per-token cross-head attention (2 tokens/block, fp16 in/out)
    attn2_kernel<<<MTOK / 2, 256>>>();

    // 5. output projection (HMMA, fp32 out): [32768,1024] @ [1024,1024] + b
    hmma_gemm_kernel<float><<<dim3(DM_ / BN, MTOK / BM), 256, SMTOT>>>(
        cp, w2, b_out, out, DM_);
}

// round 15
// speedup vs baseline: 1.0948x; 1.0189x over previous
#include <cuda_runtime.h>
#include <cuda_fp16.h>
#include <math.h>
#include <stdint.h>

// ---------------------------------------------------------------- constants
#define B_    8
#define L_    4096
#define H_    16
#define DH_   64
#define DM_   1024
#define MTOK  (B_ * L_)          // 32768
#define QKVN  (3 * H_ * DH_)     // 3072
#define KDIM  1024

// ---------------------------------------------------------------- scratch
__device__ __align__(16) __half g_qkvh[(size_t)MTOK * QKVN];  // fp16 qkv (201 MB)
__device__ float  g_pe[L_ * DH_];
__device__ __align__(16) __half g_x[(size_t)MTOK * DM_];      // x -> fp16
__device__ __align__(16) __half g_c[(size_t)MTOK * DM_];      // attn-out fp16
__device__ __align__(16) __half g_w1[(size_t)QKVN * DM_];     // w_qkv^T fp16
__device__ __align__(16) __half g_w2[(size_t)DM_ * DM_];      // w_out^T fp16

// ---------------------------------------------------------------- helpers
__device__ __forceinline__ uint32_t smem_u32(const void* p) {
    uint32_t a;
    asm("{ .reg .u64 t; cvta.to.shared.u64 t, %1; cvt.u32.u64 %0, t; }" : "=r"(a) : "l"(p));
    return a;
}
__device__ __forceinline__ void cp16(uint32_t dst, const void* src) {
    asm volatile("cp.async.cg.shared.global [%0], [%1], 16;" :: "r"(dst), "l"(src));
}
#define CP_COMMIT() asm volatile("cp.async.commit_group;" ::: "memory")
#define CP_WAIT1()  asm volatile("cp.async.wait_group 1;" ::: "memory")

__device__ __forceinline__ void ldm_x4(uint32_t* r, uint32_t addr) {
    asm volatile("ldmatrix.sync.aligned.m8n8.x4.shared.b16 {%0,%1,%2,%3}, [%4];"
                 : "=r"(r[0]), "=r"(r[1]), "=r"(r[2]), "=r"(r[3]) : "r"(addr));
}
__device__ __forceinline__ void mma16816(float* c, const uint32_t* a, const uint32_t* b) {
    asm volatile(
        "mma.sync.aligned.m16n8k16.row.col.f32.f16.f16.f32 "
        "{%0,%1,%2,%3}, {%4,%5,%6,%7}, {%8,%9}, {%0,%1,%2,%3};"
        : "+f"(c[0]), "+f"(c[1]), "+f"(c[2]), "+f"(c[3])
        : "r"(a[0]), "r"(a[1]), "r"(a[2]), "r"(a[3]), "r"(b[0]), "r"(b[1]));
}

// ---------------------------------------------------------------- pe table
__global__ void pe_init_kernel() {
    int idx = blockIdx.x * blockDim.x + threadIdx.x;
    if (idx >= L_ * (DH_ / 2)) return;
    int l = idx >> 5;
    int j = idx & 31;
    float c    = (float)(-9.210340371976184 / 64.0);
    float argf = c * (float)(2 * j);
    float dtf  = (float)exp((double)argf);
    float angf = (float)((double)l * (double)dtf);
    double ang = (double)angf;
    g_pe[l * DH_ + 2 * j]     = (float)sin(ang);
    g_pe[l * DH_ + 2 * j + 1] = (float)cos(ang);
}

// ---------------------------------------------------------------- casts
__global__ void cast_f2h_kernel(const float* __restrict__ in,
                                __half* __restrict__ out, int n4) {
    int i = blockIdx.x * blockDim.x + threadIdx.x;
    if (i >= n4) return;
    float4 v = ((const float4*)in)[i];
    ((__half2*)out)[2 * i]     = __floats2half2_rn(v.x, v.y);
    ((__half2*)out)[2 * i + 1] = __floats2half2_rn(v.z, v.w);
}

// transpose [K,N] -> [N,K] + fp16 cast.  block (32,8), grid (N/32, K/32)
__global__ void transpose_cast_kernel(const float* __restrict__ w,
                                      __half* __restrict__ t,
                                      int K, int N) {
    __shared__ float tile[32][33];
    int nb = blockIdx.x * 32, kb = blockIdx.y * 32;
    int tx = threadIdx.x, ty = threadIdx.y;
#pragma unroll
    for (int j = 0; j < 4; j++)
        tile[ty + 8 * j][tx] = w[(size_t)(kb + ty + 8 * j) * N + nb + tx];
    __syncthreads();
#pragma unroll
    for (int j = 0; j < 4; j++) {
        int n = nb + ty + 8 * j;
        int k = kb + tx;
        t[(size_t)n * K + k] = __float2half(tile[tx][ty + 8 * j]);
    }
}

// ---------------------------------------------------------------- HMMA GEMM
// C[M,N] = A[M,1024](fp16) @ B[N,1024]^T(fp16) + bias.  OutT in {__half,float}.
// CTA tile 128x128, 4 warps (2x2), warp tile 64x64, KB=64, 3-stage cp.async,
// 2 CTAs/SM.  Single barrier per iter, prefetch issued before MMA section.
#define BM    128
#define BN    128
#define KB    64
#define NITER (KDIM / KB)        // 16
#define ROWH  72                 // 64 halfs + pad 8
#define ROWB  (ROWH * 2)         // 144 bytes
#define TILEB (BM * ROWB)        // 18432 B
#define STB   (2 * TILEB)        // A + B = 36864 B
#define SMTOT (3 * STB)          // 110592 B
#define NTHR  128

__device__ __forceinline__ void cp_tile(uint32_t s_tile, const __half* g,
                                        int kc, int tid) {
    int r0 = tid >> 3;           // 0..15
    int c  = tid & 7;
    const __half* gp = g + (size_t)r0 * KDIM + kc * KB + c * 8;
    uint32_t sp = s_tile + (uint32_t)r0 * ROWB + c * 16;
#pragma unroll
    for (int i = 0; i < 8; i++)
        cp16(sp + i * 16 * ROWB, gp + (size_t)(i * 16) * KDIM);
}

template<typename OutT>
__global__ __launch_bounds__(NTHR, 2)
void hmma_gemm_kernel(const __half* __restrict__ A,
                      const __half* __restrict__ B,
                      const float* __restrict__ bias,
                      OutT* __restrict__ C,
                      int ncols)
{
    extern __shared__ __align__(16) char smem[];
    const uint32_t sb = smem_u32(smem);
    const int tid  = threadIdx.x;
    const int wid  = tid >> 5;
    const int lane = tid & 31;
    const int wrow = wid >> 1;       // 0..1 (64 rows each)
    const int wcol = wid & 1;        // 0..1 (64 cols each)
    const int bm   = blockIdx.y * BM;
    const int bn   = blockIdx.x * BN;

    const __half* gA = A + (size_t)bm * KDIM;
    const __half* gB = B + (size_t)bn * KDIM;

    float acc[4][8][4];
#pragma unroll
    for (int i = 0; i < 4; i++)
#pragma unroll
        for (int j = 0; j < 8; j++)
#pragma unroll
            for (int k = 0; k < 4; k++) acc[i][j][k] = 0.0f;

    const uint32_t a_row  = (uint32_t)(wrow * 64 + (lane & 15));
    const uint32_t a_col  = (uint32_t)((lane >> 4) * 8);
    const uint32_t b_row4 = (uint32_t)(wcol * 64 + (lane >> 4) * 8 + (lane & 7));
    const uint32_t b_col4 = (uint32_t)(((lane >> 3) & 1) * 8);

#define LOADST(buf, kc) do {                                    \
        uint32_t s0 = sb + (buf) * STB;                         \
        cp_tile(s0,         gA, (kc), tid);                     \
        cp_tile(s0 + TILEB, gB, (kc), tid);                     \
    } while (0)

    LOADST(0, 0); CP_COMMIT();
    LOADST(1, 1); CP_COMMIT();

    for (int it = 0; it < NITER; ++it) {
        CP_WAIT1();
        __syncthreads();
        int buf = it % 3;
        int pre = (buf + 2) % 3;
        if (it + 2 < NITER) LOADST(pre, it + 2);
        CP_COMMIT();

        uint32_t s0 = sb + buf * STB;
        uint32_t sA = s0;
        uint32_t sB = s0 + TILEB;

#pragma unroll
        for (int ks = 0; ks < 4; ks++) {
            uint32_t af[4][4], bf[4][4];
            uint32_t acol = (uint32_t)(ks * 32) + a_col * 2;
            uint32_t bcol = (uint32_t)(ks * 32) + b_col4 * 2;
#pragma unroll
            for (int ma = 0; ma < 4; ma++)
                ldm_x4(af[ma], sA + (a_row + ma * 16) * ROWB + acol);
#pragma unroll
            for (int nb2 = 0; nb2 < 4; nb2++)
                ldm_x4(bf[nb2], sB + (b_row4 + nb2 * 16) * ROWB + bcol);
#pragma unroll
            for (int ma = 0; ma < 4; ma++)
#pragma unroll
                for (int na = 0; na < 8; na++)
                    mma16816(acc[ma][na], af[ma], &bf[na >> 1][(na & 1) * 2]);
        }
    }

    // epilogue: bias + store (fp32 or fp16)
    const int qr = lane >> 2;
    const int qc = (lane & 3) * 2;
#pragma unroll
    for (int na = 0; na < 8; na++) {
        int col = bn + wcol * 64 + na * 8 + qc;
        float bx = bias[col], by = bias[col + 1];
#pragma unroll
        for (int ma = 0; ma < 4; ma++) {
            int r0 = bm + wrow * 64 + ma * 16 + qr;
            if constexpr (sizeof(OutT) == 2) {
                __half* Ch = (__half*)C;
                *(__half2*)(Ch + (size_t)r0 * ncols + col) =
                    __floats2half2_rn(acc[ma][na][0] + bx, acc[ma][na][1] + by);
                *(__half2*)(Ch + (size_t)(r0 + 8) * ncols + col) =
                    __floats2half2_rn(acc[ma][na][2] + bx, acc[ma][na][3] + by);
            } else {
                float* Cf = (float*)C;
                *(float2*)(Cf + (size_t)r0 * ncols + col) =
                    make_float2(acc[ma][na][0] + bx, acc[ma][na][1] + by);
                *(float2*)(Cf + (size_t)(r0 + 8) * ncols + col) =
                    make_float2(acc[ma][na][2] + bx, acc[ma][na][3] + by);
            }
        }
    }
}

// ---------------------------------------------------------------- attention
// one 256-thread block per token; fp16 qkv in, fp16 out for GEMM2
__global__ __launch_bounds__(256)
void attn_kernel() {
    __shared__ __align__(16) __half s[QKVN];
    __shared__ float spe[DH_];
    __shared__ float s_logit[256];
    __shared__ float s_prob[256];

    const int tok = blockIdx.x;
    const int l   = tok & (L_ - 1);
    const int tid = threadIdx.x;

    const uint4* row = (const uint4*)(g_qkvh + (size_t)tok * QKVN);
    uint4* s4 = (uint4*)s;
    for (int i = tid; i < QKVN * 2 / 16; i += 256)
        s4[i] = row[i];
    if (tid < DH_) spe[tid] = g_pe[l * DH_ + tid];
    __syncthreads();

    {
        const int h  = tid >> 4, gg = tid & 15;
        const __half2* q  = (const __half2*)&s[h * 192];
        const __half2* kk = (const __half2*)&s[gg * 192 + 64];
        const float2*  p2 = (const float2*)spe;
        float a = 0.0f;
#pragma unroll
        for (int i = 0; i < 32; i++) {
            int d2 = (i + gg * 2) & 31;
            float2 qf = __half22float2(q[d2]);
            float2 kf = __half22float2(kk[d2]);
            float2 pf = p2[d2];
            a += qf.x * (kf.x + pf.x) + qf.y * (kf.y + pf.y);
        }
        s_logit[tid] = a * 0.125f;
    }
    __syncthreads();

    if (tid < H_) {
        float m = -1e30f;
#pragma unroll
        for (int gg = 0; gg < 16; gg++) m = fmaxf(m, s_logit[tid * 16 + gg]);
        float p[16];
        float sum = 0.0f;
#pragma unroll
        for (int gg = 0; gg < 16; gg++) {
            p[gg] = expf(s_logit[tid * 16 + gg] - m);
            sum += p[gg];
        }
        float inv = 1.0f / sum;
#pragma unroll
        for (int gg = 0; gg < 16; gg++) s_prob[tid * 16 + gg] = p[gg] * inv;
    }
    __syncthreads();

    __half2* orow = (__half2*)(g_c + (size_t)tok * DM_);
    for (int idx = tid; idx < 512; idx += 256) {
        int h = idx >> 5, d2 = idx & 31;
        float ax = 0.0f, ay = 0.0f;
#pragma unroll
        for (int gg = 0; gg < 16; gg++) {
            float2 vf = __half22float2(((const __half2*)&s[gg * 192 + 128])[d2]);
            float p = s_prob[h * 16 + gg];
            ax += p * vf.x;
            ay += p * vf.y;
        }
        orow[idx] = __floats2half2_rn(ax, ay);
    }
}

// ---------------------------------------------------------------- launch
extern "C" void kernel_launch(void* const* d_in, const int* in_sizes, int n_in,
                              void* d_out, int out_size)
{
    (void)in_sizes; (void)n_in; (void)out_size;
    const float* x     = (const float*)d_in[0];
    const float* w_qkv = (const float*)d_in[1];
    const float* b_qkv = (const float*)d_in[2];
    const float* w_out = (const float*)d_in[3];
    const float* b_out = (const float*)d_in[4];
    float* out = (float*)d_out;

    __half *qkv_p, *xp, *cp, *w1, *w2;
    cudaGetSymbolAddress((void**)&qkv_p, g_qkvh);
    cudaGetSymbolAddress((void**)&xp, g_x);
    cudaGetSymbolAddress((void**)&cp, g_c);
    cudaGetSymbolAddress((void**)&w1, g_w1);
    cudaGetSymbolAddress((void**)&w2, g_w2);

    static bool attr_done = false;
    if (!attr_done) {
        cudaFuncSetAttribute(hmma_gemm_kernel<__half>,
                             cudaFuncAttributeMaxDynamicSharedMemorySize, SMTOT);
        cudaFuncSetAttribute(hmma_gemm_kernel<float>,
                             cudaFuncAttributeMaxDynamicSharedMemorySize, SMTOT);
        attr_done = true;
    }

    // 1. positional-encoding table
    pe_init_kernel<<<(L_ * (DH_ / 2) + 255) / 256, 256>>>();

    // 2. casts / weight transpose
    int n4 = MTOK * DM_ / 4;
    cast_f2h_kernel<<<(n4 + 255) / 256, 256>>>(x, xp, n4);
    transpose_cast_kernel<<<dim3(QKVN / 32, KDIM / 32), dim3(32, 8)>>>(w_qkv, w1, KDIM, QKVN);
    transpose_cast_kernel<<<dim3(DM_ / 32, KDIM / 32), dim3(32, 8)>>>(w_out, w2, KDIM, DM_);

    // 3. qkv projection (HMMA, fp16 out): [32768,1024] @ [1024,3072] + b
    hmma_gemm_kernel<__half><<<dim3(QKVN / BN, MTOK / BM), NTHR, SMTOT>>>(
        xp, w1, b_qkv, qkv_p, QKVN);

    // 4. per-token cross-head attention (fp16 in/out)
    attn_kernel<<<MTOK, 256>>>();

    // 5. output projection (HMMA, fp32 out): [32768,1024] @ [1024,1024] + b
    hmma_gemm_kernel<float><<<dim3(DM_ / BN, MTOK / BM), NTHR, SMTOT>>>(
        cp, w2, b_out, out, DM_);
}

// round 16
// speedup vs baseline: 1.0952x; 1.0004x over previous
#include <cuda_runtime.h>
#include <cuda_fp16.h>
#include <math.h>
#include <stdint.h>

// ---------------------------------------------------------------- constants
#define B_    8
#define L_    4096
#define H_    16
#define DH_   64
#define DM_   1024
#define MTOK  (B_ * L_)          // 32768
#define QKVN  (3 * H_ * DH_)     // 3072
#define KDIM  1024

// ---------------------------------------------------------------- scratch
__device__ __align__(16) __half g_qkvh[(size_t)MTOK * QKVN];  // fp16 qkv (201 MB)
__device__ float  g_pe[L_ * DH_];
__device__ __align__(16) __half g_x[(size_t)MTOK * DM_];      // x -> fp16
__device__ __align__(16) __half g_c[(size_t)MTOK * DM_];      // attn-out fp16
__device__ __align__(16) __half g_w1[(size_t)QKVN * DM_];     // w_qkv^T fp16
__device__ __align__(16) __half g_w2[(size_t)DM_ * DM_];      // w_out^T fp16

// ---------------------------------------------------------------- helpers
__device__ __forceinline__ uint32_t smem_u32(const void* p) {
    uint32_t a;
    asm("{ .reg .u64 t; cvta.to.shared.u64 t, %1; cvt.u32.u64 %0, t; }" : "=r"(a) : "l"(p));
    return a;
}
__device__ __forceinline__ void cp16(uint32_t dst, const void* src) {
    asm volatile("cp.async.cg.shared.global [%0], [%1], 16;" :: "r"(dst), "l"(src));
}
#define CP_COMMIT() asm volatile("cp.async.commit_group;" ::: "memory")
#define CP_WAIT1()  asm volatile("cp.async.wait_group 1;" ::: "memory")

__device__ __forceinline__ void ldm_x4(uint32_t* r, uint32_t addr) {
    asm volatile("ldmatrix.sync.aligned.m8n8.x4.shared.b16 {%0,%1,%2,%3}, [%4];"
                 : "=r"(r[0]), "=r"(r[1]), "=r"(r[2]), "=r"(r[3]) : "r"(addr));
}
__device__ __forceinline__ void mma16816(float* c, const uint32_t* a, const uint32_t* b) {
    asm volatile(
        "mma.sync.aligned.m16n8k16.row.col.f32.f16.f16.f32 "
        "{%0,%1,%2,%3}, {%4,%5,%6,%7}, {%8,%9}, {%0,%1,%2,%3};"
        : "+f"(c[0]), "+f"(c[1]), "+f"(c[2]), "+f"(c[3])
        : "r"(a[0]), "r"(a[1]), "r"(a[2]), "r"(a[3]), "r"(b[0]), "r"(b[1]));
}

// ---------------------------------------------------------------- pe table
__global__ void pe_init_kernel() {
    int idx = blockIdx.x * blockDim.x + threadIdx.x;
    if (idx >= L_ * (DH_ / 2)) return;
    int l = idx >> 5;
    int j = idx & 31;
    float c    = (float)(-9.210340371976184 / 64.0);
    float argf = c * (float)(2 * j);
    float dtf  = (float)exp((double)argf);
    float angf = (float)((double)l * (double)dtf);
    double ang = (double)angf;
    g_pe[l * DH_ + 2 * j]     = (float)sin(ang);
    g_pe[l * DH_ + 2 * j + 1] = (float)cos(ang);
}

// ---------------------------------------------------------------- casts
__global__ void cast_f2h_kernel(const float* __restrict__ in,
                                __half* __restrict__ out, int n4) {
    int i = blockIdx.x * blockDim.x + threadIdx.x;
    if (i >= n4) return;
    float4 v = ((const float4*)in)[i];
    ((__half2*)out)[2 * i]     = __floats2half2_rn(v.x, v.y);
    ((__half2*)out)[2 * i + 1] = __floats2half2_rn(v.z, v.w);
}

// transpose [K,N] -> [N,K] + fp16 cast.  block (32,8), grid (N/32, K/32)
__global__ void transpose_cast_kernel(const float* __restrict__ w,
                                      __half* __restrict__ t,
                                      int K, int N) {
    __shared__ float tile[32][33];
    int nb = blockIdx.x * 32, kb = blockIdx.y * 32;
    int tx = threadIdx.x, ty = threadIdx.y;
#pragma unroll
    for (int j = 0; j < 4; j++)
        tile[ty + 8 * j][tx] = w[(size_t)(kb + ty + 8 * j) * N + nb + tx];
    __syncthreads();
#pragma unroll
    for (int j = 0; j < 4; j++) {
        int n = nb + ty + 8 * j;
        int k = kb + tx;
        t[(size_t)n * K + k] = __float2half(tile[tx][ty + 8 * j]);
    }
}

// ---------------------------------------------------------------- HMMA GEMM
// C[M,N] = A[M,1024](fp16) @ B[N,1024]^T(fp16) + bias.  OutT in {__half,float}.
// CTA tile 128x128, 4 warps (2x2), warp tile 64x64, KB=64, 3-stage cp.async,
// 2 CTAs/SM.  Register-level fragment double-buffering: load ks+1 frags
// while issuing ks MMAs.
#define BM    128
#define BN    128
#define KB    64
#define NITER (KDIM / KB)        // 16
#define ROWH  72                 // 64 halfs + pad 8
#define ROWB  (ROWH * 2)         // 144 bytes
#define TILEB (BM * ROWB)        // 18432 B
#define STB   (2 * TILEB)        // A + B = 36864 B
#define SMTOT (3 * STB)          // 110592 B
#define NTHR  128

__device__ __forceinline__ void cp_tile(uint32_t s_tile, const __half* g,
                                        int kc, int tid) {
    int r0 = tid >> 3;           // 0..15
    int c  = tid & 7;
    const __half* gp = g + (size_t)r0 * KDIM + kc * KB + c * 8;
    uint32_t sp = s_tile + (uint32_t)r0 * ROWB + c * 16;
#pragma unroll
    for (int i = 0; i < 8; i++)
        cp16(sp + i * 16 * ROWB, gp + (size_t)(i * 16) * KDIM);
}

template<typename OutT>
__global__ __launch_bounds__(NTHR, 2)
void hmma_gemm_kernel(const __half* __restrict__ A,
                      const __half* __restrict__ B,
                      const float* __restrict__ bias,
                      OutT* __restrict__ C,
                      int ncols)
{
    extern __shared__ __align__(16) char smem[];
    const uint32_t sb = smem_u32(smem);
    const int tid  = threadIdx.x;
    const int wid  = tid >> 5;
    const int lane = tid & 31;
    const int wrow = wid >> 1;       // 0..1 (64 rows each)
    const int wcol = wid & 1;        // 0..1 (64 cols each)
    const int bm   = blockIdx.y * BM;
    const int bn   = blockIdx.x * BN;

    const __half* gA = A + (size_t)bm * KDIM;
    const __half* gB = B + (size_t)bn * KDIM;

    float acc[4][8][4];
#pragma unroll
    for (int i = 0; i < 4; i++)
#pragma unroll
        for (int j = 0; j < 8; j++)
#pragma unroll
            for (int k = 0; k < 4; k++) acc[i][j][k] = 0.0f;

    const uint32_t a_row  = (uint32_t)(wrow * 64 + (lane & 15));
    const uint32_t a_col  = (uint32_t)((lane >> 4) * 8);
    const uint32_t b_row4 = (uint32_t)(wcol * 64 + (lane >> 4) * 8 + (lane & 7));
    const uint32_t b_col4 = (uint32_t)(((lane >> 3) & 1) * 8);

#define LOADST(buf, kc) do {                                    \
        uint32_t s0 = sb + (buf) * STB;                         \
        cp_tile(s0,         gA, (kc), tid);                     \
        cp_tile(s0 + TILEB, gB, (kc), tid);                     \
    } while (0)

    LOADST(0, 0); CP_COMMIT();
    LOADST(1, 1); CP_COMMIT();

    for (int it = 0; it < NITER; ++it) {
        CP_WAIT1();
        __syncthreads();
        int buf = it % 3;
        int pre = (buf + 2) % 3;
        if (it + 2 < NITER) LOADST(pre, it + 2);
        CP_COMMIT();

        uint32_t s0 = sb + buf * STB;
        uint32_t sA = s0;
        uint32_t sB = s0 + TILEB;

        // register double-buffered fragments
        uint32_t af[2][4][4], bf[2][4][4];

#define LDFRAG(fb, ks) do {                                                     \
            uint32_t acol = (uint32_t)((ks) * 32) + a_col * 2;                  \
            uint32_t bcol = (uint32_t)((ks) * 32) + b_col4 * 2;                 \
            _Pragma("unroll")                                                   \
            for (int ma = 0; ma < 4; ma++)                                      \
                ldm_x4(af[fb][ma], sA + (a_row + ma * 16) * ROWB + acol);       \
            _Pragma("unroll")                                                   \
            for (int nb2 = 0; nb2 < 4; nb2++)                                   \
                ldm_x4(bf[fb][nb2], sB + (b_row4 + nb2 * 16) * ROWB + bcol);    \
        } while (0)

        LDFRAG(0, 0);
#pragma unroll
        for (int ks = 0; ks < 4; ks++) {
            if (ks < 3) LDFRAG((ks + 1) & 1, ks + 1);
            const int cb = ks & 1;
#pragma unroll
            for (int ma = 0; ma < 4; ma++)
#pragma unroll
                for (int na = 0; na < 8; na++)
                    mma16816(acc[ma][na], af[cb][ma], &bf[cb][na >> 1][(na & 1) * 2]);
        }
#undef LDFRAG
    }

    // epilogue: bias + store (fp32 or fp16)
    const int qr = lane >> 2;
    const int qc = (lane & 3) * 2;
#pragma unroll
    for (int na = 0; na < 8; na++) {
        int col = bn + wcol * 64 + na * 8 + qc;
        float bx = bias[col], by = bias[col + 1];
#pragma unroll
        for (int ma = 0; ma < 4; ma++) {
            int r0 = bm + wrow * 64 + ma * 16 + qr;
            if constexpr (sizeof(OutT) == 2) {
                __half* Ch = (__half*)C;
                *(__half2*)(Ch + (size_t)r0 * ncols + col) =
                    __floats2half2_rn(acc[ma][na][0] + bx, acc[ma][na][1] + by);
                *(__half2*)(Ch + (size_t)(r0 + 8) * ncols + col) =
                    __floats2half2_rn(acc[ma][na][2] + bx, acc[ma][na][3] + by);
            } else {
                float* Cf = (float*)C;
                *(float2*)(Cf + (size_t)r0 * ncols + col) =
                    make_float2(acc[ma][na][0] + bx, acc[ma][na][1] + by);
                *(float2*)(Cf + (size_t)(r0 + 8) * ncols + col) =
                    make_float2(acc[ma][na][2] + bx, acc[ma][na][3] + by);
            }
        }
    }
}

// ---------------------------------------------------------------- attention
// one 256-thread block per token; fp16 qkv in, fp16 out for GEMM2
__global__ __launch_bounds__(256)
void attn_kernel() {
    __shared__ __align__(16) __half s[QKVN];
    __shared__ float spe[DH_];
    __shared__ float s_logit[256];
    __shared__ float s_prob[256];

    const int tok = blockIdx.x;
    const int l   = tok & (L_ - 1);
    const int tid = threadIdx.x;

    const uint4* row = (const uint4*)(g_qkvh + (size_t)tok * QKVN);
    uint4* s4 = (uint4*)s;
    for (int i = tid; i < QKVN * 2 / 16; i += 256)
        s4[i] = row[i];
    if (tid < DH_) spe[tid] = g_pe[l * DH_ + tid];
    __syncthreads();

    {
        const int h  = tid >> 4, gg = tid & 15;
        const __half2* q  = (const __half2*)&s[h * 192];
        const __half2* kk = (const __half2*)&s[gg * 192 + 64];
        const float2*  p2 = (const float2*)spe;
        float a = 0.0f;
#pragma unroll
        for (int i = 0; i < 32; i++) {
            int d2 = (i + gg * 2) & 31;
            float2 qf = __half22float2(q[d2]);
            float2 kf = __half22float2(kk[d2]);
            float2 pf = p2[d2];
            a += qf.x * (kf.x + pf.x) + qf.y * (kf.y + pf.y);
        }
        s_logit[tid] = a * 0.125f;
    }
    __syncthreads();

    if (tid < H_) {
        float m = -1e30f;
#pragma unroll
        for (int gg = 0; gg < 16; gg++) m = fmaxf(m, s_logit[tid * 16 + gg]);
        float p[16];
        float sum = 0.0f;
#pragma unroll
        for (int gg = 0; gg < 16; gg++) {
            p[gg] = expf(s_logit[tid * 16 + gg] - m);
            sum += p[gg];
        }
        float inv = 1.0f / sum;
#pragma unroll
        for (int gg = 0; gg < 16; gg++) s_prob[tid * 16 + gg] = p[gg] * inv;
    }
    __syncthreads();

    __half2* orow = (__half2*)(g_c + (size_t)tok * DM_);
    for (int idx = tid; idx < 512; idx += 256) {
        int h = idx >> 5, d2 = idx & 31;
        float ax = 0.0f, ay = 0.0f;
#pragma unroll
        for (int gg = 0; gg < 16; gg++) {
            float2 vf = __half22float2(((const __half2*)&s[gg * 192 + 128])[d2]);
            float p = s_prob[h * 16 + gg];
            ax += p * vf.x;
            ay += p * vf.y;
        }
        orow[idx] = __floats2half2_rn(ax, ay);
    }
}

// ---------------------------------------------------------------- launch
extern "C" void kernel_launch(void* const* d_in, const int* in_sizes, int n_in,
                              void* d_out, int out_size)
{
    (void)in_sizes; (void)n_in; (void)out_size;
    const float* x     = (const float*)d_in[0];
    const float* w_qkv = (const float*)d_in[1];
    const float* b_qkv = (const float*)d_in[2];
    const float* w_out = (const float*)d_in[3];
    const float* b_out = (const float*)d_in[4];
    float* out = (float*)d_out;

    __half *qkv_p, *xp, *cp, *w1, *w2;
    cudaGetSymbolAddress((void**)&qkv_p, g_qkvh);
    cudaGetSymbolAddress((void**)&xp, g_x);
    cudaGetSymbolAddress((void**)&cp, g_c);
    cudaGetSymbolAddress((void**)&w1, g_w1);
    cudaGetSymbolAddress((void**)&w2, g_w2);

    static bool attr_done = false;
    if (!attr_done) {
        cudaFuncSetAttribute(hmma_gemm_kernel<__half>,
                             cudaFuncAttributeMaxDynamicSharedMemorySize, SMTOT);
        cudaFuncSetAttribute(hmma_gemm_kernel<float>,
                             cudaFuncAttributeMaxDynamicSharedMemorySize, SMTOT);
        attr_done = true;
    }

    // 1. positional-encoding table
    pe_init_kernel<<<(L_ * (DH_ / 2) + 255) / 256, 256>>>();

    // 2. casts / weight transpose
    int n4 = MTOK * DM_ / 4;
    cast_f2h_kernel<<<(n4 + 255) / 256, 256>>>(x, xp, n4);
    transpose_cast_kernel<<<dim3(QKVN / 32, KDIM / 32), dim3(32, 8)>>>(w_qkv, w1, KDIM, QKVN);
    transpose_cast_kernel<<<dim3(DM_ / 32, KDIM / 32), dim3(32, 8)>>>(w_out, w2, KDIM, DM_);

    // 3. qkv projection (HMMA, fp16 out): [32768,1024] @ [1024,3072] + b
    hmma_gemm_kernel<__half><<<dim3(QKVN / BN, MTOK / BM), NTHR, SMTOT>>>(
        xp, w1, b_qkv, qkv_p, QKVN);

    // 4. per-token cross-head attention (fp16 in/out)
    attn_kernel<<<MTOK, 256>>>();

    // 5. output projection (HMMA, fp32 out): [32768,1024] @ [1024,1024] + b
    hmma_gemm_kernel<float><<<dim3(DM_ / BN, MTOK / BM), NTHR, SMTOT>>>(
        cp, w2, b_out, out, DM_);
}

// round 17
// speedup vs baseline: 1.2234x; 1.1170x over previous
#include <cuda_runtime.h>
#include <cuda_fp16.h>
#include <math.h>
#include <stdint.h>

// ---------------------------------------------------------------- constants
#define B_    8
#define L_    4096
#define H_    16
#define DH_   64
#define DM_   1024
#define MTOK  (B_ * L_)          // 32768
#define QKVN  (3 * H_ * DH_)     // 3072
#define KDIM  1024

// ---------------------------------------------------------------- scratch
__device__ __align__(16) __half g_qkvh[(size_t)MTOK * QKVN];  // fp16 qkv (201 MB)
__device__ float  g_pe[L_ * DH_];
__device__ __align__(16) __half g_x[(size_t)MTOK * DM_];      // x -> fp16
__device__ __align__(16) __half g_c[(size_t)MTOK * DM_];      // attn-out fp16
__device__ __align__(16) __half g_w1[(size_t)QKVN * DM_];     // w_qkv^T fp16
__device__ __align__(16) __half g_w2[(size_t)DM_ * DM_];      // w_out^T fp16

// ---------------------------------------------------------------- helpers
__device__ __forceinline__ uint32_t smem_u32(const void* p) {
    uint32_t a;
    asm("{ .reg .u64 t; cvta.to.shared.u64 t, %1; cvt.u32.u64 %0, t; }" : "=r"(a) : "l"(p));
    return a;
}
__device__ __forceinline__ void cp16(uint32_t dst, const void* src) {
    asm volatile("cp.async.cg.shared.global [%0], [%1], 16;" :: "r"(dst), "l"(src));
}
#define CP_COMMIT() asm volatile("cp.async.commit_group;" ::: "memory")
#define CP_WAIT1()  asm volatile("cp.async.wait_group 1;" ::: "memory")

__device__ __forceinline__ void ldm_x4(uint32_t* r, uint32_t addr) {
    asm volatile("ldmatrix.sync.aligned.m8n8.x4.shared.b16 {%0,%1,%2,%3}, [%4];"
                 : "=r"(r[0]), "=r"(r[1]), "=r"(r[2]), "=r"(r[3]) : "r"(addr));
}
__device__ __forceinline__ void mma16816(float* c, const uint32_t* a, const uint32_t* b) {
    asm volatile(
        "mma.sync.aligned.m16n8k16.row.col.f32.f16.f16.f32 "
        "{%0,%1,%2,%3}, {%4,%5,%6,%7}, {%8,%9}, {%0,%1,%2,%3};"
        : "+f"(c[0]), "+f"(c[1]), "+f"(c[2]), "+f"(c[3])
        : "r"(a[0]), "r"(a[1]), "r"(a[2]), "r"(a[3]), "r"(b[0]), "r"(b[1]));
}

// ---------------------------------------------------------------- fused prep
// One kernel: x cast -> fp16, w_qkv / w_out transpose+cast, pe table.
#define CAST_BLKS (MTOK * DM_ / 4 / 256)          // 32768
#define W1T_BX    (QKVN / 32)                     // 96
#define W1T_BLKS  (W1T_BX * (KDIM / 32))          // 3072
#define W2T_BX    (DM_ / 32)                      // 32
#define W2T_BLKS  (W2T_BX * (KDIM / 32))          // 1024
#define PE_BLKS   (L_ * (DH_ / 2) / 256)          // 512
#define PREP_BLKS (CAST_BLKS + W1T_BLKS + W2T_BLKS + PE_BLKS)

__device__ __forceinline__ void transpose_body(const float* __restrict__ w,
                                               __half* __restrict__ t,
                                               int N, int bx, int by,
                                               float (*tile)[33], int tid) {
    int tx = tid & 31, ty = tid >> 5;
    int nb = bx * 32, kb = by * 32;
#pragma unroll
    for (int j = 0; j < 4; j++)
        tile[ty + 8 * j][tx] = w[(size_t)(kb + ty + 8 * j) * N + nb + tx];
    __syncthreads();
#pragma unroll
    for (int j = 0; j < 4; j++) {
        int n = nb + ty + 8 * j;
        int k = kb + tx;
        t[(size_t)n * KDIM + k] = __float2half(tile[tx][ty + 8 * j]);
    }
}

__global__ __launch_bounds__(256)
void prep_kernel(const float* __restrict__ x,
                 const float* __restrict__ w_qkv,
                 const float* __restrict__ w_out) {
    __shared__ float tile[32][33];
    const int b   = blockIdx.x;
    const int tid = threadIdx.x;

    if (b < CAST_BLKS) {
        int i = b * 256 + tid;
        float4 v = ((const float4*)x)[i];
        ((__half2*)g_x)[2 * i]     = __floats2half2_rn(v.x, v.y);
        ((__half2*)g_x)[2 * i + 1] = __floats2half2_rn(v.z, v.w);
    } else if (b < CAST_BLKS + W1T_BLKS) {
        int idx = b - CAST_BLKS;
        transpose_body(w_qkv, g_w1, QKVN, idx % W1T_BX, idx / W1T_BX, tile, tid);
    } else if (b < CAST_BLKS + W1T_BLKS + W2T_BLKS) {
        int idx = b - CAST_BLKS - W1T_BLKS;
        transpose_body(w_out, g_w2, DM_, idx % W2T_BX, idx / W2T_BX, tile, tid);
    } else {
        int idx = (b - CAST_BLKS - W1T_BLKS - W2T_BLKS) * 256 + tid;
        int l = idx >> 5;
        int j = idx & 31;
        float c    = (float)(-9.210340371976184 / 64.0);
        float argf = c * (float)(2 * j);
        float dtf  = (float)exp((double)argf);
        float angf = (float)((double)l * (double)dtf);
        double ang = (double)angf;
        g_pe[l * DH_ + 2 * j]     = (float)sin(ang);
        g_pe[l * DH_ + 2 * j + 1] = (float)cos(ang);
    }
}

// ---------------------------------------------------------------- HMMA GEMM
// C[M,N] = A[M,1024](fp16) @ B[N,1024]^T(fp16) + bias.  OutT in {__half,float}.
// CTA tile 128x128, 4 warps (2x2), warp tile 64x64, KB=64, 3-stage cp.async,
// 2 CTAs/SM.  Frag double-buffering; cp.async spread across ks-steps.
#define BM    128
#define BN    128
#define KB    64
#define NITER (KDIM / KB)        // 16
#define ROWH  72                 // 64 halfs + pad 8
#define ROWB  (ROWH * 2)         // 144 bytes
#define TILEB (BM * ROWB)        // 18432 B
#define STB   (2 * TILEB)        // A + B = 36864 B
#define SMTOT (3 * STB)          // 110592 B
#define NTHR  128

__device__ __forceinline__ void cp_tile(uint32_t s_tile, const __half* g,
                                        int kc, int tid) {
    int r0 = tid >> 3;           // 0..15
    int c  = tid & 7;
    const __half* gp = g + (size_t)r0 * KDIM + kc * KB + c * 8;
    uint32_t sp = s_tile + (uint32_t)r0 * ROWB + c * 16;
#pragma unroll
    for (int i = 0; i < 8; i++)
        cp16(sp + i * 16 * ROWB, gp + (size_t)(i * 16) * KDIM);
}

// one quarter (ks-step q) of a stage load: 2 A-row groups + 2 B-row groups
__device__ __forceinline__ void cp_quarter(uint32_t s_stage,
                                           const __half* gA, const __half* gB,
                                           int kc, int tid, int q) {
    int r0 = tid >> 3;           // 0..15
    int c  = tid & 7;
    size_t gofs = (size_t)r0 * KDIM + (size_t)kc * KB + c * 8;
    uint32_t sofs = (uint32_t)r0 * ROWB + c * 16;
#pragma unroll
    for (int i = 2 * q; i < 2 * q + 2; i++) {
        cp16(s_stage + sofs + i * 16 * ROWB,         gA + gofs + (size_t)(i * 16) * KDIM);
        cp16(s_stage + TILEB + sofs + i * 16 * ROWB, gB + gofs + (size_t)(i * 16) * KDIM);
    }
}

template<typename OutT>
__global__ __launch_bounds__(NTHR, 2)
void hmma_gemm_kernel(const __half* __restrict__ A,
                      const __half* __restrict__ B,
                      const float* __restrict__ bias,
                      OutT* __restrict__ C,
                      int ncols)
{
    extern __shared__ __align__(16) char smem[];
    const uint32_t sb = smem_u32(smem);
    const int tid  = threadIdx.x;
    const int wid  = tid >> 5;
    const int lane = tid & 31;
    const int wrow = wid >> 1;       // 0..1 (64 rows each)
    const int wcol = wid & 1;        // 0..1 (64 cols each)
    const int bm   = blockIdx.y * BM;
    const int bn   = blockIdx.x * BN;

    const __half* gA = A + (size_t)bm * KDIM;
    const __half* gB = B + (size_t)bn * KDIM;

    float acc[4][8][4];
#pragma unroll
    for (int i = 0; i < 4; i++)
#pragma unroll
        for (int j = 0; j < 8; j++)
#pragma unroll
            for (int k = 0; k < 4; k++) acc[i][j][k] = 0.0f;

    const uint32_t a_row  = (uint32_t)(wrow * 64 + (lane & 15));
    const uint32_t a_col  = (uint32_t)((lane >> 4) * 8);
    const uint32_t b_row4 = (uint32_t)(wcol * 64 + (lane >> 4) * 8 + (lane & 7));
    const uint32_t b_col4 = (uint32_t)(((lane >> 3) & 1) * 8);

    // prologue: fill stages 0 and 1 fully
    cp_tile(sb,                 gA, 0, tid);
    cp_tile(sb + TILEB,         gB, 0, tid);
    CP_COMMIT();
    cp_tile(sb + STB,           gA, 1, tid);
    cp_tile(sb + STB + TILEB,   gB, 1, tid);
    CP_COMMIT();

    for (int it = 0; it < NITER; ++it) {
        CP_WAIT1();
        __syncthreads();
        const int buf = it % 3;
        const int pre = (buf + 2) % 3;
        const bool do_pre = (it + 2 < NITER);
        const uint32_t sp0 = sb + pre * STB;
        const int kc = it + 2;

        uint32_t s0 = sb + buf * STB;
        uint32_t sA = s0;
        uint32_t sB = s0 + TILEB;

        uint32_t af[2][4][4], bf[2][4][4];

#define LDFRAG(fb, ks) do {                                                     \
            uint32_t acol = (uint32_t)((ks) * 32) + a_col * 2;                  \
            uint32_t bcol = (uint32_t)((ks) * 32) + b_col4 * 2;                 \
            _Pragma("unroll")                                                   \
            for (int ma = 0; ma < 4; ma++)                                      \
                ldm_x4(af[fb][ma], sA + (a_row + ma * 16) * ROWB + acol);       \
            _Pragma("unroll")                                                   \
            for (int nb2 = 0; nb2 < 4; nb2++)                                   \
                ldm_x4(bf[fb][nb2], sB + (b_row4 + nb2 * 16) * ROWB + bcol);    \
        } while (0)

        LDFRAG(0, 0);
#pragma unroll
        for (int ks = 0; ks < 4; ks++) {
            if (ks < 3) LDFRAG((ks + 1) & 1, ks + 1);
            if (do_pre) cp_quarter(sp0, gA, gB, kc, tid, ks);   // 4 cp16/step
            const int cb = ks & 1;
#pragma unroll
            for (int ma = 0; ma < 4; ma++)
#pragma unroll
                for (int na = 0; na < 8; na++)
                    mma16816(acc[ma][na], af[cb][ma], &bf[cb][na >> 1][(na & 1) * 2]);
        }
#undef LDFRAG
        CP_COMMIT();
    }

    // epilogue: bias + store (fp32 or fp16)
    const int qr = lane >> 2;
    const int qc = (lane & 3) * 2;
#pragma unroll
    for (int na = 0; na < 8; na++) {
        int col = bn + wcol * 64 + na * 8 + qc;
        float bx = bias[col], by = bias[col + 1];
#pragma unroll
        for (int ma = 0; ma < 4; ma++) {
            int r0 = bm + wrow * 64 + ma * 16 + qr;
            if constexpr (sizeof(OutT) == 2) {
                __half* Ch = (__half*)C;
                *(__half2*)(Ch + (size_t)r0 * ncols + col) =
                    __floats2half2_rn(acc[ma][na][0] + bx, acc[ma][na][1] + by);
                *(__half2*)(Ch + (size_t)(r0 + 8) * ncols + col) =
                    __floats2half2_rn(acc[ma][na][2] + bx, acc[ma][na][3] + by);
            } else {
                float* Cf = (float*)C;
                *(float2*)(Cf + (size_t)r0 * ncols + col) =
                    make_float2(acc[ma][na][0] + bx, acc[ma][na][1] + by);
                *(float2*)(Cf + (size_t)(r0 + 8) * ncols + col) =
                    make_float2(acc[ma][na][2] + bx, acc[ma][na][3] + by);
            }
        }
    }
}

// ---------------------------------------------------------------- attention
// one 256-thread block per token; fp16 qkv in, fp16 out for GEMM2
__global__ __launch_bounds__(256)
void attn_kernel() {
    __shared__ __align__(16) __half s[QKVN];
    __shared__ float spe[DH_];
    __shared__ float s_logit[256];
    __shared__ float s_prob[256];

    const int tok = blockIdx.x;
    const int l   = tok & (L_ - 1);
    const int tid = threadIdx.x;

    const uint4* row = (const uint4*)(g_qkvh + (size_t)tok * QKVN);
    uint4* s4 = (uint4*)s;
    for (int i = tid; i < QKVN * 2 / 16; i += 256)
        s4[i] = row[i];
    if (tid < DH_) spe[tid] = g_pe[l * DH_ + tid];
    __syncthreads();

    {
        const int h  = tid >> 4, gg = tid & 15;
        const __half2* q  = (const __half2*)&s[h * 192];
        const __half2* kk = (const __half2*)&s[gg * 192 + 64];
        const float2*  p2 = (const float2*)spe;
        float a = 0.0f;
#pragma unroll
        for (int i = 0; i < 32; i++) {
            int d2 = (i + gg * 2) & 31;
            float2 qf = __half22float2(q[d2]);
            float2 kf = __half22float2(kk[d2]);
            float2 pf = p2[d2];
            a += qf.x * (kf.x + pf.x) + qf.y * (kf.y + pf.y);
        }
        s_logit[tid] = a * 0.125f;
    }
    __syncthreads();

    if (tid < H_) {
        float m = -1e30f;
#pragma unroll
        for (int gg = 0; gg < 16; gg++) m = fmaxf(m, s_logit[tid * 16 + gg]);
        float p[16];
        float sum = 0.0f;
#pragma unroll
        for (int gg = 0; gg < 16; gg++) {
            p[gg] = expf(s_logit[tid * 16 + gg] - m);
            sum += p[gg];
        }
        float inv = 1.0f / sum;
#pragma unroll
        for (int gg = 0; gg < 16; gg++) s_prob[tid * 16 + gg] = p[gg] * inv;
    }
    __syncthreads();

    __half2* orow = (__half2*)(g_c + (size_t)tok * DM_);
    for (int idx = tid; idx < 512; idx += 256) {
        int h = idx >> 5, d2 = idx & 31;
        float ax = 0.0f, ay = 0.0f;
#pragma unroll
        for (int gg = 0; gg < 16; gg++) {
            float2 vf = __half22float2(((const __half2*)&s[gg * 192 + 128])[d2]);
            float p = s_prob[h * 16 + gg];
            ax += p * vf.x;
            ay += p * vf.y;
        }
        orow[idx] = __floats2half2_rn(ax, ay);
    }
}

// ---------------------------------------------------------------- launch
extern "C" void kernel_launch(void* const* d_in, const int* in_sizes, int n_in,
                              void* d_out, int out_size)
{
    (void)in_sizes; (void)n_in; (void)out_size;
    const float* x     = (const float*)d_in[0];
    const float* w_qkv = (const float*)d_in[1];
    const float* b_qkv = (const float*)d_in[2];
    const float* w_out = (const float*)d_in[3];
    const float* b_out = (const float*)d_in[4];
    float* out = (float*)d_out;

    __half *qkv_p, *xp, *cp, *w1, *w2;
    cudaGetSymbolAddress((void**)&qkv_p, g_qkvh);
    cudaGetSymbolAddress((void**)&xp, g_x);
    cudaGetSymbolAddress((void**)&cp, g_c);
    cudaGetSymbolAddress((void**)&w1, g_w1);
    cudaGetSymbolAddress((void**)&w2, g_w2);

    static bool attr_done = false;
    if (!attr_done) {
        cudaFuncSetAttribute(hmma_gemm_kernel<__half>,
                             cudaFuncAttributeMaxDynamicSharedMemorySize, SMTOT);
        cudaFuncSetAttribute(hmma_gemm_kernel<float>,
                             cudaFuncAttributeMaxDynamicSharedMemorySize, SMTOT);
        attr_done = true;
    }

    // 1. fused prep: x cast + weight transposes + pe table (one launch)
    prep_kernel<<<PREP_BLKS, 256>>>(x, w_qkv, w_out);

    // 2. qkv projection (HMMA, fp16 out): [32768,1024] @ [1024,3072] + b
    hmma_gemm_kernel<__half><<<dim3(QKVN / BN, MTOK / BM), NTHR, SMTOT>>>(
        xp, w1, b_qkv, qkv_p, QKVN);

    // 3. per-token cross-head attention (fp16 in/out)
    attn_kernel<<<MTOK, 256>>>();

    // 4. output projection (HMMA, fp32 out): [32768,1024] @ [1024,1024] + b
    hmma_gemm_kernel<float><<<dim3(DM_ / BN, MTOK / BM), NTHR, SMTOT>>>(
        cp, w2, b_out, out, DM_);
}